// round 13
// baseline (speedup 1.0000x reference)
#include <cuda_runtime.h>
#include <cuda_fp16.h>
#include <cstdint>

#define S_NODES 100000
#define T_NODES 20000
#define E_EDGES 1000000
#define SRC_DIM 256
#define EMB_DIM 128
#define TGT_DIM 128

#define NB 125           // persistent blocks for fused CSR kernel (125*160 = 20000)
#define CHUNK 160        // targets per block in scan phase

// Scratch (__device__ globals; no allocations allowed)
__device__ uint32_t g_y[S_NODES * (TGT_DIM / 2)];  // 25.6 MB  y rows as 64 half2
__device__ float    g_M[SRC_DIM * TGT_DIM];        // 128 KB   M = embed @ weight
__device__ int      g_cnt[T_NODES + 1];            // last slot = grid-barrier counter
__device__ int      g_off[T_NODES];
__device__ int      g_bsum[NB];
__device__ int      g_base[NB];
__device__ int      g_rank[E_EDGES];               // 4 MB  per-edge rank within target
__device__ int      g_bucket[E_EDGES];

// ===========================================================================
// software grid barrier (counter zeroed by host memset before each launch)
// ===========================================================================
__device__ __forceinline__ void gbar(unsigned target) {
    __syncthreads();
    if (threadIdx.x == 0) {
        __threadfence();
        atomicAdd(&g_cnt[T_NODES], 1);
        while ((unsigned)atomicAdd(&g_cnt[T_NODES], 0) < target) {}
        __threadfence();
    }
    __syncthreads();
}

// block-wide inclusive scan of per-thread value v (1024 threads); returns incl
__device__ __forceinline__ int block_scan_incl(int v, int* wsum) {
    const int lane = threadIdx.x & 31;
    const int w    = threadIdx.x >> 5;
    int incl = v;
#pragma unroll
    for (int d = 1; d < 32; d <<= 1) {
        int t = __shfl_up_sync(0xFFFFFFFF, incl, d);
        if (lane >= d) incl += t;
    }
    if (lane == 31) wsum[w] = incl;
    __syncthreads();
    if (w == 0) {
        int t = (lane < 32) ? wsum[lane] : 0;
#pragma unroll
        for (int d = 1; d < 32; d <<= 1) {
            int u = __shfl_up_sync(0xFFFFFFFF, t, d);
            if (lane >= d) t += u;
        }
        wsum[lane] = t;
    }
    __syncthreads();
    if (w > 0) incl += wsum[w - 1];
    return incl;
}

// ===========================================================================
// fused CSR builder: hist+rank -> scan -> fill, one persistent kernel
// requires g_cnt[0..T_NODES] zeroed before launch (host memset)
// ===========================================================================
__global__ void __launch_bounds__(1024)
csr_kernel(const int* __restrict__ src, const int* __restrict__ dst) {
    __shared__ int wsum[32];
    const int b   = blockIdx.x;
    const int tid = threadIdx.x;
    const int gtid = b * 1024 + tid;
    const int nthreads = NB * 1024;

    // P1: histogram + rank (4-way unrolled atomics)
    for (int base = gtid * 4; base < E_EDGES; base += nthreads * 4) {
        int d0 = -1, d1 = -1, d2 = -1, d3 = -1;
        if (base + 0 < E_EDGES) d0 = dst[base + 0];
        if (base + 1 < E_EDGES) d1 = dst[base + 1];
        if (base + 2 < E_EDGES) d2 = dst[base + 2];
        if (base + 3 < E_EDGES) d3 = dst[base + 3];
        int r0 = (d0 >= 0) ? atomicAdd(&g_cnt[d0], 1) : 0;
        int r1 = (d1 >= 0) ? atomicAdd(&g_cnt[d1], 1) : 0;
        int r2 = (d2 >= 0) ? atomicAdd(&g_cnt[d2], 1) : 0;
        int r3 = (d3 >= 0) ? atomicAdd(&g_cnt[d3], 1) : 0;
        if (d0 >= 0) g_rank[base + 0] = r0;
        if (d1 >= 0) g_rank[base + 1] = r1;
        if (d2 >= 0) g_rank[base + 2] = r2;
        if (d3 >= 0) g_rank[base + 3] = r3;
    }
    gbar(NB);

    // P2: per-block local exclusive scan of its CHUNK of counts
    {
        int v = (tid < CHUNK) ? g_cnt[b * CHUNK + tid] : 0;
        int incl = block_scan_incl(v, wsum);
        if (tid < CHUNK) g_off[b * CHUNK + tid] = incl - v;   // local exclusive
        if (tid == CHUNK - 1) g_bsum[b] = incl;               // block total
    }
    gbar(2 * NB);

    // P3: block 0 scans the NB block totals
    if (b == 0) {
        int v = (tid < NB) ? g_bsum[tid] : 0;
        int incl = block_scan_incl(v, wsum);
        if (tid < NB) g_base[tid] = incl - v;
    }
    gbar(3 * NB);

    // P4: add block base to local offsets
    if (tid < CHUNK) g_off[b * CHUNK + tid] += g_base[b];
    gbar(4 * NB);

    // P5: atomic-free fill
    for (int i = gtid; i < E_EDGES; i += nthreads) {
        int d = dst[i];
        g_bucket[g_off[d] + g_rank[i]] = src[i];
    }
}

// ===========================================================================
// M[k][n] = sum_e embed[k][e] * weight[e][n]
// ===========================================================================
__global__ void __launch_bounds__(128)
m_kernel(const float* __restrict__ embed, const float* __restrict__ weight) {
    __shared__ float er[EMB_DIM];
    int k = blockIdx.x;
    int n = threadIdx.x;
    if (n < EMB_DIM) er[n] = embed[k * EMB_DIM + n];
    __syncthreads();
    float acc = 0.f;
#pragma unroll 8
    for (int e = 0; e < EMB_DIM; e++)
        acc += er[e] * weight[e * TGT_DIM + n];
    g_M[k * TGT_DIM + n] = acc;
}

// ===========================================================================
// yGEMM via mma.sync tf32 (m16n8k8). Epilogue: scale by 1/xnorm, pack half2.
// BM=128, BN=128, BK=32, 256 threads, warp tile 32x64.
// ===========================================================================
__device__ __forceinline__ uint32_t cvt_tf32(float f) {
    uint32_t r;
    asm("cvt.rna.tf32.f32 %0, %1;" : "=r"(r) : "f"(f));
    return r;
}

__global__ void __launch_bounds__(256)
ygemm_kernel(const float* __restrict__ sf, const float* __restrict__ xnorm) {
    __shared__ uint32_t As[128][36];
    __shared__ uint32_t Bs[32][136];

    const int tid  = threadIdx.x;
    const int wid  = tid >> 5;
    const int lane = tid & 31;
    const int warp_m = wid & 3;
    const int warp_n = wid >> 2;
    const int grp = lane >> 2;
    const int qd  = lane & 3;
    const int row0 = blockIdx.x * 128;

    float c[2][8][4];
#pragma unroll
    for (int mf = 0; mf < 2; mf++)
#pragma unroll
        for (int nf = 0; nf < 8; nf++)
#pragma unroll
            for (int j = 0; j < 4; j++) c[mf][nf][j] = 0.f;

    for (int kb = 0; kb < SRC_DIM; kb += 32) {
#pragma unroll
        for (int l = 0; l < 4; l++) {
            int idx = tid + 256 * l;
            int r   = idx >> 3;
            int q   = idx & 7;
            int grow = row0 + r;
            float4 v = make_float4(0.f, 0.f, 0.f, 0.f);
            if (grow < S_NODES)
                v = *(const float4*)(sf + (size_t)grow * SRC_DIM + kb + q * 4);
            As[r][q * 4 + 0] = cvt_tf32(v.x);
            As[r][q * 4 + 1] = cvt_tf32(v.y);
            As[r][q * 4 + 2] = cvt_tf32(v.z);
            As[r][q * 4 + 3] = cvt_tf32(v.w);
        }
#pragma unroll
        for (int l = 0; l < 4; l++) {
            int idx = tid + 256 * l;
            int r   = idx >> 5;
            int q   = idx & 31;
            float4 v = *(const float4*)(g_M + (size_t)(kb + r) * TGT_DIM + q * 4);
            Bs[r][q * 4 + 0] = cvt_tf32(v.x);
            Bs[r][q * 4 + 1] = cvt_tf32(v.y);
            Bs[r][q * 4 + 2] = cvt_tf32(v.z);
            Bs[r][q * 4 + 3] = cvt_tf32(v.w);
        }
        __syncthreads();

#pragma unroll
        for (int k8 = 0; k8 < 32; k8 += 8) {
            uint32_t a[2][4];
#pragma unroll
            for (int mf = 0; mf < 2; mf++) {
                int rbase = warp_m * 32 + mf * 16;
                a[mf][0] = As[rbase + grp    ][k8 + qd    ];
                a[mf][1] = As[rbase + grp + 8][k8 + qd    ];
                a[mf][2] = As[rbase + grp    ][k8 + qd + 4];
                a[mf][3] = As[rbase + grp + 8][k8 + qd + 4];
            }
            uint32_t b[8][2];
#pragma unroll
            for (int nf = 0; nf < 8; nf++) {
                int nbase = warp_n * 64 + nf * 8 + grp;
                b[nf][0] = Bs[k8 + qd    ][nbase];
                b[nf][1] = Bs[k8 + qd + 4][nbase];
            }
#pragma unroll
            for (int mf = 0; mf < 2; mf++)
#pragma unroll
                for (int nf = 0; nf < 8; nf++) {
                    asm volatile(
                        "mma.sync.aligned.m16n8k8.row.col.f32.tf32.tf32.f32 "
                        "{%0,%1,%2,%3}, {%4,%5,%6,%7}, {%8,%9}, {%0,%1,%2,%3};"
                        : "+f"(c[mf][nf][0]), "+f"(c[mf][nf][1]),
                          "+f"(c[mf][nf][2]), "+f"(c[mf][nf][3])
                        : "r"(a[mf][0]), "r"(a[mf][1]), "r"(a[mf][2]), "r"(a[mf][3]),
                          "r"(b[nf][0]), "r"(b[nf][1]));
                }
        }
        __syncthreads();
    }

    // epilogue: scale by 1/xnorm, pack adjacent-n pair into half2
#pragma unroll
    for (int mf = 0; mf < 2; mf++) {
        int r_lo = row0 + warp_m * 32 + mf * 16 + grp;
        int r_hi = r_lo + 8;
        float inv_lo = (r_lo < S_NODES) ? (1.0f / xnorm[r_lo]) : 0.f;
        float inv_hi = (r_hi < S_NODES) ? (1.0f / xnorm[r_hi]) : 0.f;
#pragma unroll
        for (int nf = 0; nf < 8; nf++) {
            int col = warp_n * 64 + nf * 8 + qd * 2;
            if (r_lo < S_NODES) {
                __half2 h = __floats2half2_rn(c[mf][nf][0] * inv_lo,
                                              c[mf][nf][1] * inv_lo);
                g_y[(size_t)r_lo * 64 + (col >> 1)] = *(uint32_t*)&h;
            }
            if (r_hi < S_NODES) {
                __half2 h = __floats2half2_rn(c[mf][nf][2] * inv_hi,
                                              c[mf][nf][3] * inv_hi);
                g_y[(size_t)r_hi * 64 + (col >> 1)] = *(uint32_t*)&h;
            }
        }
    }
}

// ===========================================================================
// gather: out[t] = mean over edges of y[src]  (warp/target; lane = 4 dims)
// ===========================================================================
__device__ __forceinline__ void acc_u2(float4& a, uint2 u) {
    float2 lo = __half22float2(*(__half2*)&u.x);
    float2 hi = __half22float2(*(__half2*)&u.y);
    a.x += lo.x; a.y += lo.y; a.z += hi.x; a.w += hi.y;
}

__global__ void __launch_bounds__(256)
gather_kernel(float* __restrict__ out) {
    int warp = (blockIdx.x * blockDim.x + threadIdx.x) >> 5;
    int lane = threadIdx.x & 31;
    if (warp >= T_NODES) return;

    int beg = g_off[warp];
    int n   = g_cnt[warp];
    const uint2* yb = (const uint2*)g_y;

    float4 a0 = make_float4(0.f, 0.f, 0.f, 0.f);
    float4 a1 = a0, a2 = a0, a3 = a0;

    int i = 0;
    for (; i + 4 <= n; i += 4) {
        int s0 = g_bucket[beg + i + 0];
        int s1 = g_bucket[beg + i + 1];
        int s2 = g_bucket[beg + i + 2];
        int s3 = g_bucket[beg + i + 3];
        uint2 v0 = yb[(size_t)s0 * 32 + lane];
        uint2 v1 = yb[(size_t)s1 * 32 + lane];
        uint2 v2 = yb[(size_t)s2 * 32 + lane];
        uint2 v3 = yb[(size_t)s3 * 32 + lane];
        acc_u2(a0, v0); acc_u2(a1, v1); acc_u2(a2, v2); acc_u2(a3, v3);
    }
    for (; i < n; i++) {
        int s = g_bucket[beg + i];
        acc_u2(a0, yb[(size_t)s * 32 + lane]);
    }

    float inv = 1.0f / (float)(n > 1 ? n : 1);
    float4 r;
    r.x = (a0.x + a1.x + a2.x + a3.x) * inv;
    r.y = (a0.y + a1.y + a2.y + a3.y) * inv;
    r.z = (a0.z + a1.z + a2.z + a3.z) * inv;
    r.w = (a0.w + a1.w + a2.w + a3.w) * inv;
    ((float4*)out)[(size_t)warp * 32 + lane] = r;
}

// ===========================================================================
extern "C" void kernel_launch(void* const* d_in, const int* in_sizes, int n_in,
                              void* d_out, int out_size) {
    const float* source_feat = (const float*)d_in[0];  // [N, 256]
    const int*   src_idx     = (const int*)d_in[1];    // [E]
    const int*   dst_idx     = (const int*)d_in[2];    // [E]
    // d_in[3] = range_list (unused)
    const float* x_norm      = (const float*)d_in[4];  // [N]
    const float* embed       = (const float*)d_in[5];  // [256, 128]
    const float* weight      = (const float*)d_in[6];  // [128, 128]
    float* out = (float*)d_out;                        // [T, 128]

    static cudaStream_t s_side = nullptr;
    static cudaEvent_t ev_fork = nullptr, ev_join = nullptr;
    if (!s_side) {  // created on the uncaptured correctness call, reused under capture
        cudaStreamCreateWithFlags(&s_side, cudaStreamNonBlocking);
        cudaEventCreateWithFlags(&ev_fork, cudaEventDisableTiming);
        cudaEventCreateWithFlags(&ev_join, cudaEventDisableTiming);
    }

    // fork first so the memset overlaps the side-stream GEMM chain
    cudaEventRecord(ev_fork, 0);
    cudaStreamWaitEvent(s_side, ev_fork, 0);

    m_kernel<<<SRC_DIM, 128, 0, s_side>>>(embed, weight);
    ygemm_kernel<<<(S_NODES + 127) / 128, 256, 0, s_side>>>(source_feat, x_norm);

    int* gcnt;
    cudaGetSymbolAddress((void**)&gcnt, g_cnt);
    cudaMemsetAsync(gcnt, 0, (T_NODES + 1) * sizeof(int), 0);  // counts + barrier

    csr_kernel<<<NB, 1024>>>(src_idx, dst_idx);

    // join
    cudaEventRecord(ev_join, s_side);
    cudaStreamWaitEvent(0, ev_join, 0);

    gather_kernel<<<(T_NODES * 32 + 255) / 256, 256>>>(out);
}

// round 14
// speedup vs baseline: 1.2336x; 1.2336x over previous
#include <cuda_runtime.h>
#include <cuda_fp16.h>
#include <cstdint>

#define S_NODES 100000
#define T_NODES 20000
#define E_EDGES 1000000
#define SRC_DIM 256
#define EMB_DIM 128
#define TGT_DIM 128

// Scratch (__device__ globals; no allocations allowed)
__device__ uint32_t g_y[S_NODES * (TGT_DIM / 2)];  // 25.6 MB  y rows as 64 half2
__device__ float    g_M[SRC_DIM * TGT_DIM];        // 128 KB   M = embed @ weight
__device__ int      g_cnt[T_NODES];
__device__ int      g_off[T_NODES];
__device__ int      g_rank[E_EDGES];               // 4 MB  per-edge rank within target
__device__ int      g_bucket[E_EDGES];

// ===========================================================================
// histogram + rank, 4-way unrolled for atomic MLP
// ===========================================================================
__global__ void __launch_bounds__(256)
hist_rank_kernel(const int* __restrict__ dst) {
    int tid = blockIdx.x * blockDim.x + threadIdx.x;
    int nthreads = gridDim.x * blockDim.x;
    for (int base = tid * 4; base < E_EDGES; base += nthreads * 4) {
        int d0 = -1, d1 = -1, d2 = -1, d3 = -1;
        if (base + 0 < E_EDGES) d0 = dst[base + 0];
        if (base + 1 < E_EDGES) d1 = dst[base + 1];
        if (base + 2 < E_EDGES) d2 = dst[base + 2];
        if (base + 3 < E_EDGES) d3 = dst[base + 3];
        int r0 = (d0 >= 0) ? atomicAdd(&g_cnt[d0], 1) : 0;
        int r1 = (d1 >= 0) ? atomicAdd(&g_cnt[d1], 1) : 0;
        int r2 = (d2 >= 0) ? atomicAdd(&g_cnt[d2], 1) : 0;
        int r3 = (d3 >= 0) ? atomicAdd(&g_cnt[d3], 1) : 0;
        if (d0 >= 0) g_rank[base + 0] = r0;
        if (d1 >= 0) g_rank[base + 1] = r1;
        if (d2 >= 0) g_rank[base + 2] = r2;
        if (d3 >= 0) g_rank[base + 3] = r3;
    }
}

// ===========================================================================
// exclusive scan of g_cnt -> g_off (single block, smem-staged, padded)
// ===========================================================================
__global__ void __launch_bounds__(1024)
scan_kernel() {
    extern __shared__ int s[];            // padded b -> b + b/20
    __shared__ int wsum[32];
    const int tid  = threadIdx.x;
    const int lane = tid & 31;
    const int w    = tid >> 5;
    const int PER  = 20;

    for (int i = tid; i < T_NODES; i += 1024) s[i + i / 20] = g_cnt[i];
    __syncthreads();

    int p = tid * 21;
    int nvalid = T_NODES - tid * PER;
    int sum = 0;
#pragma unroll
    for (int j = 0; j < PER; j++) {
        if (j < nvalid) {
            int v = s[p + j];
            s[p + j] = sum;
            sum += v;
        }
    }

    int incl = sum;
#pragma unroll
    for (int d = 1; d < 32; d <<= 1) {
        int t = __shfl_up_sync(0xFFFFFFFF, incl, d);
        if (lane >= d) incl += t;
    }
    if (lane == 31) wsum[w] = incl;
    __syncthreads();
    if (w == 0) {
        int v = wsum[lane];
#pragma unroll
        for (int d = 1; d < 32; d <<= 1) {
            int t = __shfl_up_sync(0xFFFFFFFF, v, d);
            if (lane >= d) v += t;
        }
        wsum[lane] = v;
    }
    __syncthreads();

    int offset = (incl - sum) + (w > 0 ? wsum[w - 1] : 0);
#pragma unroll
    for (int j = 0; j < PER; j++) {
        if (j < nvalid) s[p + j] += offset;
    }
    __syncthreads();

    for (int i = tid; i < T_NODES; i += 1024) g_off[i] = s[i + i / 20];
}

// ===========================================================================
// atomic-free bucket fill using precomputed ranks
// ===========================================================================
__global__ void __launch_bounds__(256)
fill_kernel(const int* __restrict__ src, const int* __restrict__ dst) {
    int stride = gridDim.x * blockDim.x;
    for (int i = blockIdx.x * blockDim.x + threadIdx.x; i < E_EDGES; i += stride) {
        int d = dst[i];
        g_bucket[g_off[d] + g_rank[i]] = src[i];
    }
}

// ===========================================================================
// M[k][n] = sum_e embed[k][e] * weight[e][n]
// ===========================================================================
__global__ void __launch_bounds__(128)
m_kernel(const float* __restrict__ embed, const float* __restrict__ weight) {
    __shared__ float er[EMB_DIM];
    int k = blockIdx.x;
    int n = threadIdx.x;
    if (n < EMB_DIM) er[n] = embed[k * EMB_DIM + n];
    __syncthreads();
    float acc = 0.f;
#pragma unroll 8
    for (int e = 0; e < EMB_DIM; e++)
        acc += er[e] * weight[e * TGT_DIM + n];
    g_M[k * TGT_DIM + n] = acc;
}

// ===========================================================================
// yGEMM via mma.sync tf32 (m16n8k8), cp.async double-buffered pipeline.
// Raw fp32 tiles in smem; rna->tf32 conversion at fragment load.
// BM=128, BN=128, BK=32, 256 threads, warp tile 32x64.
// ===========================================================================
__device__ __forceinline__ uint32_t cvt_tf32(float f) {
    uint32_t r;
    asm("cvt.rna.tf32.f32 %0, %1;" : "=r"(r) : "f"(f));
    return r;
}
__device__ __forceinline__ uint32_t cvt_tf32_bits(uint32_t bits) {
    return cvt_tf32(__uint_as_float(bits));
}
__device__ __forceinline__ void cp_async16(uint32_t saddr, const void* gptr, int src_bytes) {
    asm volatile("cp.async.cg.shared.global [%0], [%1], 16, %2;"
                 :: "r"(saddr), "l"(gptr), "r"(src_bytes) : "memory");
}
__device__ __forceinline__ void cp_commit() {
    asm volatile("cp.async.commit_group;" ::: "memory");
}
template <int N>
__device__ __forceinline__ void cp_wait() {
    asm volatile("cp.async.wait_group %0;" :: "n"(N) : "memory");
}

#define A_STRIDE 36
#define B_STRIDE 136
#define A_STAGE (128 * A_STRIDE)          // words per A stage
#define B_STAGE (32 * B_STRIDE)
#define YG_SMEM ((2 * A_STAGE + 2 * B_STAGE) * 4)   // 71680 B

__global__ void __launch_bounds__(256)
ygemm_kernel(const float* __restrict__ sf, const float* __restrict__ xnorm) {
    extern __shared__ uint32_t dyn[];
    uint32_t* Abuf = dyn;                  // [2][128][36]
    uint32_t* Bbuf = dyn + 2 * A_STAGE;    // [2][32][136]

    const int tid  = threadIdx.x;
    const int wid  = tid >> 5;
    const int lane = tid & 31;
    const int warp_m = wid & 3;
    const int warp_n = wid >> 2;
    const int grp = lane >> 2;
    const int qd  = lane & 3;
    const int row0 = blockIdx.x * 128;

    // per-thread cp.async coords
    const int rA = tid >> 3;     // + 32*l  (A row)
    const int qA = tid & 7;      // A float4 col
    const int rB = tid >> 5;     // + 8*l   (B row)
    const int qB = tid & 31;     // B float4 col

    uint32_t aBase = (uint32_t)__cvta_generic_to_shared(Abuf);
    uint32_t bBase = (uint32_t)__cvta_generic_to_shared(Bbuf);

    // issue loads for tile `kb` into stage `st`
#define ISSUE_TILE(st, kb) do {                                                 \
        _Pragma("unroll")                                                       \
        for (int l = 0; l < 4; l++) {                                           \
            int r = rA + 32 * l;                                                \
            int grow = row0 + r;                                                \
            uint32_t da = aBase + ((st) * A_STAGE + r * A_STRIDE + qA * 4) * 4; \
            const float* ga = sf + (size_t)grow * SRC_DIM + (kb) + qA * 4;      \
            cp_async16(da, ga, (grow < S_NODES) ? 16 : 0);                      \
        }                                                                       \
        _Pragma("unroll")                                                       \
        for (int l = 0; l < 4; l++) {                                           \
            int r = rB + 8 * l;                                                 \
            uint32_t db = bBase + ((st) * B_STAGE + r * B_STRIDE + qB * 4) * 4; \
            const float* gb = g_M + (size_t)((kb) + r) * TGT_DIM + qB * 4;      \
            cp_async16(db, gb, 16);                                             \
        }                                                                       \
        cp_commit();                                                            \
    } while (0)

    float c[2][8][4];
#pragma unroll
    for (int mf = 0; mf < 2; mf++)
#pragma unroll
        for (int nf = 0; nf < 8; nf++)
#pragma unroll
            for (int j = 0; j < 4; j++) c[mf][nf][j] = 0.f;

    ISSUE_TILE(0, 0);

    for (int it = 0; it < 8; it++) {
        int st = it & 1;
        if (it < 7) ISSUE_TILE(1 - st, (it + 1) * 32);
        if (it < 7) cp_wait<1>(); else cp_wait<0>();
        __syncthreads();

        const uint32_t* As = Abuf + st * A_STAGE;
        const uint32_t* Bs = Bbuf + st * B_STAGE;

#pragma unroll
        for (int k8 = 0; k8 < 32; k8 += 8) {
            uint32_t a[2][4];
#pragma unroll
            for (int mf = 0; mf < 2; mf++) {
                int rbase = warp_m * 32 + mf * 16;
                a[mf][0] = cvt_tf32_bits(As[(rbase + grp    ) * A_STRIDE + k8 + qd    ]);
                a[mf][1] = cvt_tf32_bits(As[(rbase + grp + 8) * A_STRIDE + k8 + qd    ]);
                a[mf][2] = cvt_tf32_bits(As[(rbase + grp    ) * A_STRIDE + k8 + qd + 4]);
                a[mf][3] = cvt_tf32_bits(As[(rbase + grp + 8) * A_STRIDE + k8 + qd + 4]);
            }
            uint32_t b[8][2];
#pragma unroll
            for (int nf = 0; nf < 8; nf++) {
                int nbase = warp_n * 64 + nf * 8 + grp;
                b[nf][0] = cvt_tf32_bits(Bs[(k8 + qd    ) * B_STRIDE + nbase]);
                b[nf][1] = cvt_tf32_bits(Bs[(k8 + qd + 4) * B_STRIDE + nbase]);
            }
#pragma unroll
            for (int mf = 0; mf < 2; mf++)
#pragma unroll
                for (int nf = 0; nf < 8; nf++) {
                    asm volatile(
                        "mma.sync.aligned.m16n8k8.row.col.f32.tf32.tf32.f32 "
                        "{%0,%1,%2,%3}, {%4,%5,%6,%7}, {%8,%9}, {%0,%1,%2,%3};"
                        : "+f"(c[mf][nf][0]), "+f"(c[mf][nf][1]),
                          "+f"(c[mf][nf][2]), "+f"(c[mf][nf][3])
                        : "r"(a[mf][0]), "r"(a[mf][1]), "r"(a[mf][2]), "r"(a[mf][3]),
                          "r"(b[nf][0]), "r"(b[nf][1]));
                }
        }
        __syncthreads();
    }

    // epilogue: scale by 1/xnorm, pack adjacent-n pair into half2
#pragma unroll
    for (int mf = 0; mf < 2; mf++) {
        int r_lo = row0 + warp_m * 32 + mf * 16 + grp;
        int r_hi = r_lo + 8;
        float inv_lo = (r_lo < S_NODES) ? (1.0f / xnorm[r_lo]) : 0.f;
        float inv_hi = (r_hi < S_NODES) ? (1.0f / xnorm[r_hi]) : 0.f;
#pragma unroll
        for (int nf = 0; nf < 8; nf++) {
            int col = warp_n * 64 + nf * 8 + qd * 2;
            if (r_lo < S_NODES) {
                __half2 h = __floats2half2_rn(c[mf][nf][0] * inv_lo,
                                              c[mf][nf][1] * inv_lo);
                g_y[(size_t)r_lo * 64 + (col >> 1)] = *(uint32_t*)&h;
            }
            if (r_hi < S_NODES) {
                __half2 h = __floats2half2_rn(c[mf][nf][2] * inv_hi,
                                              c[mf][nf][3] * inv_hi);
                g_y[(size_t)r_hi * 64 + (col >> 1)] = *(uint32_t*)&h;
            }
        }
    }
}

// ===========================================================================
// gather: out[t] = mean over edges of y[src]  (warp/target; lane = 4 dims)
// ===========================================================================
__device__ __forceinline__ void acc_u2(float4& a, uint2 u) {
    float2 lo = __half22float2(*(__half2*)&u.x);
    float2 hi = __half22float2(*(__half2*)&u.y);
    a.x += lo.x; a.y += lo.y; a.z += hi.x; a.w += hi.y;
}

__global__ void __launch_bounds__(256)
gather_kernel(float* __restrict__ out) {
    int warp = (blockIdx.x * blockDim.x + threadIdx.x) >> 5;
    int lane = threadIdx.x & 31;
    if (warp >= T_NODES) return;

    int beg = g_off[warp];
    int n   = g_cnt[warp];
    const uint2* yb = (const uint2*)g_y;

    float4 a0 = make_float4(0.f, 0.f, 0.f, 0.f);
    float4 a1 = a0, a2 = a0, a3 = a0;

    int i = 0;
    for (; i + 4 <= n; i += 4) {
        int s0 = g_bucket[beg + i + 0];
        int s1 = g_bucket[beg + i + 1];
        int s2 = g_bucket[beg + i + 2];
        int s3 = g_bucket[beg + i + 3];
        uint2 v0 = yb[(size_t)s0 * 32 + lane];
        uint2 v1 = yb[(size_t)s1 * 32 + lane];
        uint2 v2 = yb[(size_t)s2 * 32 + lane];
        uint2 v3 = yb[(size_t)s3 * 32 + lane];
        acc_u2(a0, v0); acc_u2(a1, v1); acc_u2(a2, v2); acc_u2(a3, v3);
    }
    for (; i < n; i++) {
        int s = g_bucket[beg + i];
        acc_u2(a0, yb[(size_t)s * 32 + lane]);
    }

    float inv = 1.0f / (float)(n > 1 ? n : 1);
    float4 r;
    r.x = (a0.x + a1.x + a2.x + a3.x) * inv;
    r.y = (a0.y + a1.y + a2.y + a3.y) * inv;
    r.z = (a0.z + a1.z + a2.z + a3.z) * inv;
    r.w = (a0.w + a1.w + a2.w + a3.w) * inv;
    ((float4*)out)[(size_t)warp * 32 + lane] = r;
}

// ===========================================================================
extern "C" void kernel_launch(void* const* d_in, const int* in_sizes, int n_in,
                              void* d_out, int out_size) {
    const float* source_feat = (const float*)d_in[0];  // [N, 256]
    const int*   src_idx     = (const int*)d_in[1];    // [E]
    const int*   dst_idx     = (const int*)d_in[2];    // [E]
    // d_in[3] = range_list (unused)
    const float* x_norm      = (const float*)d_in[4];  // [N]
    const float* embed       = (const float*)d_in[5];  // [256, 128]
    const float* weight      = (const float*)d_in[6];  // [128, 128]
    float* out = (float*)d_out;                        // [T, 128]

    const int SCAN_SMEM = (T_NODES + T_NODES / 20) * (int)sizeof(int);  // 84 KB

    static cudaStream_t s_side = nullptr;
    static cudaEvent_t ev_fork = nullptr, ev_join = nullptr;
    if (!s_side) {  // created on the uncaptured correctness call, reused under capture
        cudaStreamCreateWithFlags(&s_side, cudaStreamNonBlocking);
        cudaEventCreateWithFlags(&ev_fork, cudaEventDisableTiming);
        cudaEventCreateWithFlags(&ev_join, cudaEventDisableTiming);
        cudaFuncSetAttribute(scan_kernel,
                             cudaFuncAttributeMaxDynamicSharedMemorySize, SCAN_SMEM);
        cudaFuncSetAttribute(ygemm_kernel,
                             cudaFuncAttributeMaxDynamicSharedMemorySize, YG_SMEM);
    }

    int* gcnt;
    cudaGetSymbolAddress((void**)&gcnt, g_cnt);
    cudaMemsetAsync(gcnt, 0, T_NODES * sizeof(int), 0);

    // fork: GEMM chain on side stream, CSR chain on main stream
    cudaEventRecord(ev_fork, 0);
    cudaStreamWaitEvent(s_side, ev_fork, 0);

    m_kernel<<<SRC_DIM, 128, 0, s_side>>>(embed, weight);
    ygemm_kernel<<<(S_NODES + 127) / 128, 256, YG_SMEM, s_side>>>(source_feat, x_norm);

    hist_rank_kernel<<<1024, 256>>>(dst_idx);
    scan_kernel<<<1, 1024, SCAN_SMEM>>>();
    fill_kernel<<<1024, 256>>>(src_idx, dst_idx);

    // join
    cudaEventRecord(ev_join, s_side);
    cudaStreamWaitEvent(0, ev_join, 0);

    gather_kernel<<<(T_NODES * 32 + 255) / 256, 256>>>(out);
}